// round 5
// baseline (speedup 1.0000x reference)
#include <cuda_runtime.h>
#include <math.h>

#define TT 128
#define NB 256
#define EE 512
#define AD 8
#define HH 512
#define H3 1536
#define TN (TT*NB)
#define TNH ((size_t)TN*HH)
#define NH (NB*HH)
#define NCTA 128
#define NGROUP 8

// Scratch (no cudaMalloc allowed)
__device__ float g_gi [(size_t)TN * H3];   // input-side gates, cell 1 (+ b_ih + b_hh[r,z])
__device__ float g_gip[(size_t)TN * H3];   // input-side gates, cell 2
__device__ float g_A [2][3][NH];           // masked hidden state, triple-buffered by t%3
__device__ unsigned g_flags[NGROUP * 16 * 32];  // per (group, producer) flag, 128B apart

__device__ __forceinline__ unsigned f2tf(float x) {
    unsigned r;
    asm("cvt.rna.tf32.f32 %0, %1;" : "=r"(r) : "f"(x));
    return r;
}

__device__ __forceinline__ void mma8(float* c, const unsigned* a, const unsigned* b) {
    asm volatile(
        "mma.sync.aligned.m16n8k8.row.col.f32.tf32.tf32.f32 "
        "{%0,%1,%2,%3},{%4,%5,%6,%7},{%8,%9},{%0,%1,%2,%3};"
        : "+f"(c[0]), "+f"(c[1]), "+f"(c[2]), "+f"(c[3])
        : "r"(a[0]), "r"(a[1]), "r"(a[2]), "r"(a[3]), "r"(b[0]), "r"(b[1]));
}

__device__ __forceinline__ float fsig(float x) {
    return 1.f / (1.f + __expf(-x));
}
__device__ __forceinline__ float ftanh(float x) {
    return 1.f - 2.f / (__expf(2.f * x) + 1.f);
}

__device__ __forceinline__ float2 ldcg2(const float* p) {
    float2 v;
    asm volatile("ld.global.cg.v2.f32 {%0,%1}, [%2];" : "=f"(v.x), "=f"(v.y) : "l"(p));
    return v;
}

// spin until *f >= target (acquire)
__device__ __forceinline__ void wait_flag(const unsigned* f, unsigned target) {
    unsigned v;
    do {
        asm volatile("ld.acquire.gpu.u32 %0, [%1];" : "=r"(v) : "l"(f));
    } while (v < target);
}

// ===========================================================================
// GI GEMM (unchanged, passing): g_gi/g_gip with biases folded
// ===========================================================================
__global__ void __launch_bounds__(256) gi_gemm_k(
    const float* __restrict__ x,
    const float* __restrict__ wih,  const float* __restrict__ wihp,
    const float* __restrict__ pah,  const float* __restrict__ masks,
    const float* __restrict__ bih,  const float* __restrict__ bihp,
    const float* __restrict__ bhh,  const float* __restrict__ bhhp)
{
    constexpr int BM = 128, BN = 128, BK = 16, SA = 20;
    constexpr int WRM = 2;
    constexpr int MT = 4, NT = 4, AV = 2, BV = 2;

    __shared__ unsigned sA[2][BM * SA];
    __shared__ unsigned sB[2][BN * SA];

    const int m0 = blockIdx.y * BM;
    const int n0 = blockIdx.x * BN;
    const float* Bg = wih + (size_t)n0 * 520;

    const int tid = threadIdx.x, lane = tid & 31, warp = tid >> 5;
    const int wm = warp % WRM, wn = warp / WRM;

    float acc[MT][NT][4];
    float acc2[MT][NT][4];
#pragma unroll
    for (int i = 0; i < MT; i++)
#pragma unroll
        for (int j = 0; j < NT; j++)
#pragma unroll
            for (int q = 0; q < 4; q++) { acc[i][j][q] = 0.f; acc2[i][j][q] = 0.f; }

    unsigned ra[AV][4], rb[BV][4];

    auto GL = [&](int kc) {
#pragma unroll
        for (int i = 0; i < AV; i++) {
            int s = tid + i * 256; int r = s >> 2; int c = (s & 3) << 2;
            float4 v = *reinterpret_cast<const float4*>(x + (size_t)(m0 + r) * EE + kc * BK + c);
            ra[i][0] = f2tf(v.x); ra[i][1] = f2tf(v.y); ra[i][2] = f2tf(v.z); ra[i][3] = f2tf(v.w);
        }
#pragma unroll
        for (int i = 0; i < BV; i++) {
            int s = tid + i * 256; int r = s >> 2; int c = (s & 3) << 2;
            float4 v = *reinterpret_cast<const float4*>(Bg + (size_t)r * 520 + kc * BK + c);
            rb[i][0] = f2tf(v.x); rb[i][1] = f2tf(v.y); rb[i][2] = f2tf(v.z); rb[i][3] = f2tf(v.w);
        }
    };
    auto SS = [&](int buf) {
#pragma unroll
        for (int i = 0; i < AV; i++) {
            int s = tid + i * 256; int r = s >> 2; int c = (s & 3) << 2;
            *reinterpret_cast<uint4*>(&sA[buf][r * SA + c]) = *reinterpret_cast<uint4*>(ra[i]);
        }
#pragma unroll
        for (int i = 0; i < BV; i++) {
            int s = tid + i * 256; int r = s >> 2; int c = (s & 3) << 2;
            *reinterpret_cast<uint4*>(&sB[buf][r * SA + c]) = *reinterpret_cast<uint4*>(rb[i]);
        }
    };
    auto COMP = [&](int buf) {
#pragma unroll
        for (int k8 = 0; k8 < BK / 8; k8++) {
            unsigned af[MT][4]; unsigned bf[NT][2];
#pragma unroll
            for (int mt = 0; mt < MT; mt++) {
                int r = wm * MT * 16 + mt * 16 + (lane >> 2);
                int c = k8 * 8 + (lane & 3);
                af[mt][0] = sA[buf][r * SA + c];
                af[mt][1] = sA[buf][(r + 8) * SA + c];
                af[mt][2] = sA[buf][r * SA + c + 4];
                af[mt][3] = sA[buf][(r + 8) * SA + c + 4];
            }
#pragma unroll
            for (int nt = 0; nt < NT; nt++) {
                int n = wn * NT * 8 + nt * 8 + (lane >> 2);
                int kk = k8 * 8 + (lane & 3);
                bf[nt][0] = sB[buf][n * SA + kk];
                bf[nt][1] = sB[buf][n * SA + kk + 4];
            }
#pragma unroll
            for (int mt = 0; mt < MT; mt++)
#pragma unroll
                for (int nt = 0; nt < NT; nt++)
                    mma8(acc[mt][nt], af[mt], bf[nt]);
        }
    };

    GL(0); SS(0); __syncthreads();
    constexpr int NKC = EE / BK;
    for (int kc = 0; kc < NKC; kc++) {
        if (kc + 1 < NKC) GL(kc + 1);
        COMP(kc & 1);
        if (kc + 1 < NKC) SS((kc + 1) & 1);
        __syncthreads();
    }

    // Tail: masked prev-action (K=8)
    {
        int s = tid;
        if (s < BM * 2) {
            int r = s >> 1; int c = (s & 1) << 2;
            float4 v = *reinterpret_cast<const float4*>(pah + (size_t)(m0 + r) * AD + c);
            float mk = masks[m0 + r];
            uint4 t4 = { f2tf(v.x * mk), f2tf(v.y * mk), f2tf(v.z * mk), f2tf(v.w * mk) };
            *reinterpret_cast<uint4*>(&sA[0][r * SA + c]) = t4;
        }
        if (s < BN * 2) {
            int n = s >> 1; int c = (s & 1) << 2;
            float4 v = *reinterpret_cast<const float4*>(wih + (size_t)(n0 + n) * 520 + 512 + c);
            uint4 t4 = { f2tf(v.x), f2tf(v.y), f2tf(v.z), f2tf(v.w) };
            *reinterpret_cast<uint4*>(&sB[0][n * SA + c]) = t4;
            float4 w = *reinterpret_cast<const float4*>(wihp + (size_t)(n0 + n) * AD + c);
            uint4 t5 = { f2tf(w.x), f2tf(w.y), f2tf(w.z), f2tf(w.w) };
            *reinterpret_cast<uint4*>(&sB[1][n * SA + c]) = t5;
        }
    }
    __syncthreads();
    {
        unsigned af2[MT][4], b0f[NT][2], b1f[NT][2];
#pragma unroll
        for (int mt = 0; mt < MT; mt++) {
            int r = wm * MT * 16 + mt * 16 + (lane >> 2);
            int c = (lane & 3);
            af2[mt][0] = sA[0][r * SA + c];
            af2[mt][1] = sA[0][(r + 8) * SA + c];
            af2[mt][2] = sA[0][r * SA + c + 4];
            af2[mt][3] = sA[0][(r + 8) * SA + c + 4];
        }
#pragma unroll
        for (int nt = 0; nt < NT; nt++) {
            int n = wn * NT * 8 + nt * 8 + (lane >> 2);
            int kk = (lane & 3);
            b0f[nt][0] = sB[0][n * SA + kk]; b0f[nt][1] = sB[0][n * SA + kk + 4];
            b1f[nt][0] = sB[1][n * SA + kk]; b1f[nt][1] = sB[1][n * SA + kk + 4];
        }
#pragma unroll
        for (int mt = 0; mt < MT; mt++)
#pragma unroll
            for (int nt = 0; nt < NT; nt++) {
                mma8(acc[mt][nt], af2[mt], b0f[nt]);
                mma8(acc2[mt][nt], af2[mt], b1f[nt]);
            }
    }

#pragma unroll
    for (int mt = 0; mt < MT; mt++)
#pragma unroll
        for (int nt = 0; nt < NT; nt++) {
            int r = m0 + wm * MT * 16 + mt * 16 + (lane >> 2);
            int c = n0 + wn * NT * 8 + nt * 8 + ((lane & 3) << 1);
            float hb0 = (c < 1024) ? bhh[c] : 0.f;
            float hb1 = (c < 1024) ? bhh[c + 1] : 0.f;
            float b0 = bih[c] + hb0, b1 = bih[c + 1] + hb1;
            *reinterpret_cast<float2*>(&g_gi[(size_t)r * H3 + c]) =
                make_float2(acc[mt][nt][0] + b0, acc[mt][nt][1] + b1);
            *reinterpret_cast<float2*>(&g_gi[(size_t)(r + 8) * H3 + c]) =
                make_float2(acc[mt][nt][2] + b0, acc[mt][nt][3] + b1);
            float pb0 = (c < 1024) ? bhhp[c] : 0.f;
            float pb1 = (c < 1024) ? bhhp[c + 1] : 0.f;
            float p0 = bihp[c] + pb0, p1 = bihp[c + 1] + pb1;
            *reinterpret_cast<float2*>(&g_gip[(size_t)r * H3 + c]) =
                make_float2(acc2[mt][nt][0] + p0, acc2[mt][nt][1] + p1);
            *reinterpret_cast<float2*>(&g_gip[(size_t)(r + 8) * H3 + c]) =
                make_float2(acc2[mt][nt][2] + p0, acc2[mt][nt][3] + p1);
        }
}

// ===========================================================================
// Persistent scan kernel. 128 CTAs x 128 threads, 1 CTA/SM.
// Per-slice producer flags + ring-ordered k-loop: no global barrier.
// A state triple-buffered (t % 3). BK=32 == one producer slice per k-chunk.
// ===========================================================================
#define SW_LD 516
#define SA_LD 36
#define SMEM_SCAN ((96*SW_LD + 3*64*SA_LD) * 4)

__global__ void __launch_bounds__(128, 1) scan_k(
    const float* __restrict__ whh, const float* __restrict__ whhp,
    const float* __restrict__ masks, const float* __restrict__ ginit,
    const float* __restrict__ bhh, const float* __restrict__ bhhp,
    float* __restrict__ out)
{
    extern __shared__ unsigned sh[];
    unsigned* sW = sh;                      // 96 x 516
    unsigned* sA = sh + 96 * SW_LD;         // 3 stages x 64 x 36

    const int bx = blockIdx.x;
    const int p  = bx & 15;                 // j-slice index == producer slot
    const int j0 = p * 32;
    const int m0 = ((bx >> 4) & 3) * 64;
    const int cell = bx >> 6;
    const int grp = bx >> 4;                // (m,cell) group, 8 groups of 16

    const float* W  = cell ? whhp : whh;
    const float* gi = cell ? g_gip : g_gi;
    const float* bh = cell ? bhhp : bhh;
    float* outs = out + (cell ? (TNH + NH) : 0);
    float* hf   = out + (cell ? (2 * TNH + NH) : TNH);
    unsigned* flags = g_flags + grp * 16 * 32;  // flags[q] at +q*32

    const int tid = threadIdx.x, lane = tid & 31, warp = tid >> 5;
    const int wm = warp & 1, wn = warp >> 1;

    // ---- preload weights into SMEM (tf32, RNA) ----
    for (int i = tid; i < 96 * 128; i += 128) {
        int rr = i >> 7, cc = (i & 127) << 2;
        int g = rr >> 5, jj = rr & 31;
        float4 v = *reinterpret_cast<const float4*>(W + (size_t)(g * HH + j0 + jj) * HH + cc);
        unsigned* d = &sW[rr * SW_LD + cc];
        d[0] = f2tf(v.x); d[1] = f2tf(v.y); d[2] = f2tf(v.z); d[3] = f2tf(v.w);
    }
    const int cb = j0 + wn * 16 + ((lane & 3) << 1);
    float2 bn2[2];
    bn2[0] = *reinterpret_cast<const float2*>(bh + 2 * HH + cb);
    bn2[1] = *reinterpret_cast<const float2*>(bh + 2 * HH + cb + 8);
    __syncthreads();

    unsigned sA_u32;
    asm("{ .reg .u64 t; cvta.to.shared.u64 t, %1; cvt.u32.u64 %0, t; }"
        : "=r"(sA_u32) : "l"(sA));

    int rb = 0;  // t % 3
    for (int t = 0; t < TT; t++) {
        int rbn = rb + 1; if (rbn >= 3) rbn -= 3;
        const float* Ard = g_A[cell][rb];
        float*       Awr = g_A[cell][rbn];
        const size_t trow = (size_t)t * NB;
        const float* As = Ard + (size_t)m0 * HH;
        const unsigned tgt = (unsigned)t;

        // cp.async for one chunk (32 cols) into stage stg
        auto issue = [&](int chunk, int stg) {
#pragma unroll
            for (int pp = 0; pp < 4; pp++) {
                int s = tid + pp * 128;
                int row = s >> 3;
                int c4 = (s & 7) << 2;
                unsigned d = sA_u32 + ((((stg * 64) + row) * SA_LD + c4) << 2);
                const float* src = As + (size_t)row * HH + chunk * 32 + c4;
                asm volatile("cp.async.cg.shared.global [%0], [%1], 16;" :: "r"(d), "l"(src));
            }
        };

        // own slice first (flag set by self; instant)
        wait_flag(&flags[p * 32], tgt);
        issue(p, 0); asm volatile("cp.async.commit_group;");

        // ---- epilogue operand prefetch (overlaps with GEMM & neighbor wait) ----
        float2 pir[4][2], piz[4][2], pin[4][2], php[4][2], pg[4][2];
        float pmask[4];
#pragma unroll
        for (int q = 0; q < 4; q++) {
            int n = m0 + wm * 32 + (q >> 1) * 16 + (lane >> 2) + (q & 1) * 8;
            size_t gb = (trow + n) * (size_t)H3 + cb;
            if (t < TT - 1) pmask[q] = masks[trow + NB + n];
            else            pmask[q] = 0.f;
#pragma unroll
            for (int nt = 0; nt < 2; nt++) {
                pir[q][nt] = *reinterpret_cast<const float2*>(gi + gb + nt * 8);
                piz[q][nt] = *reinterpret_cast<const float2*>(gi + gb + HH + nt * 8);
                pin[q][nt] = *reinterpret_cast<const float2*>(gi + gb + 2 * HH + nt * 8);
                php[q][nt] = ldcg2(Ard + (size_t)n * HH + cb + nt * 8);
                if (cell && t < TT - 1)
                    pg[q][nt] = *reinterpret_cast<const float2*>(
                        ginit + (trow + NB + n) * (size_t)HH + cb + nt * 8);
                else
                    pg[q][nt] = make_float2(0.f, 0.f);
            }
        }

        // second chunk
        {
            int c1 = (p + 1) & 15;
            wait_flag(&flags[c1 * 32], tgt);
            issue(c1, 1); asm volatile("cp.async.commit_group;");
        }

        float acc[3][2][2][4];
#pragma unroll
        for (int g = 0; g < 3; g++)
#pragma unroll
            for (int mt = 0; mt < 2; mt++)
#pragma unroll
                for (int nt = 0; nt < 2; nt++)
#pragma unroll
                    for (int q = 0; q < 4; q++) acc[g][mt][nt][q] = 0.f;

        int sr = 0;
        for (int i = 0; i < 16; i++) {
            const int chunk = (p + i) & 15;
            // flag check for chunk i+2 BEFORE draining the pipe (overlaps latency)
            int cnx = 0;
            if (i < 14) {
                cnx = (p + i + 2) & 15;
                wait_flag(&flags[cnx * 32], tgt);
            }
            asm volatile("cp.async.wait_group 1;");
            __syncthreads();
            if (i < 14) {
                int sw = sr + 2; if (sw >= 3) sw -= 3;
                issue(cnx, sw);
            }
            asm volatile("cp.async.commit_group;");
            const unsigned* sab = sA + sr * 64 * SA_LD;
#pragma unroll
            for (int k8 = 0; k8 < 4; k8++) {
                const int ck = k8 * 8 + (lane & 3);
                unsigned af[2][4];
#pragma unroll
                for (int mt = 0; mt < 2; mt++) {
                    int r = wm * 32 + mt * 16 + (lane >> 2);
                    af[mt][0] = sab[r * SA_LD + ck];
                    af[mt][1] = sab[(r + 8) * SA_LD + ck];
                    af[mt][2] = sab[r * SA_LD + ck + 4];
                    af[mt][3] = sab[(r + 8) * SA_LD + ck + 4];
                }
                const int kg = chunk * 32 + ck;
#pragma unroll
                for (int g = 0; g < 3; g++)
#pragma unroll
                    for (int nt = 0; nt < 2; nt++) {
                        int bn = g * 32 + wn * 16 + nt * 8 + (lane >> 2);
                        unsigned bf[2] = { sW[bn * SW_LD + kg], sW[bn * SW_LD + kg + 4] };
#pragma unroll
                        for (int mt = 0; mt < 2; mt++)
                            mma8(acc[g][mt][nt], af[mt], bf);
                    }
            }
            sr++; if (sr >= 3) sr -= 3;
        }

        // ---- fused gate epilogue ----
#pragma unroll
        for (int mt = 0; mt < 2; mt++)
#pragma unroll
            for (int half = 0; half < 2; half++) {
                int q = mt * 2 + half;
                int n = m0 + wm * 32 + mt * 16 + (lane >> 2) + half * 8;
                size_t mrow = trow + n;
                float mnx = pmask[q];
#pragma unroll
                for (int nt = 0; nt < 2; nt++) {
                    int c = cb + nt * 8;
                    float rr0 = fsig(pir[q][nt].x + acc[0][mt][nt][half * 2]);
                    float rr1 = fsig(pir[q][nt].y + acc[0][mt][nt][half * 2 + 1]);
                    float zz0 = fsig(piz[q][nt].x + acc[1][mt][nt][half * 2]);
                    float zz1 = fsig(piz[q][nt].y + acc[1][mt][nt][half * 2 + 1]);
                    float nn0 = ftanh(pin[q][nt].x + rr0 * (acc[2][mt][nt][half * 2] + bn2[nt].x));
                    float nn1 = ftanh(pin[q][nt].y + rr1 * (acc[2][mt][nt][half * 2 + 1] + bn2[nt].y));
                    float h0 = (1.f - zz0) * nn0 + zz0 * php[q][nt].x;
                    float h1 = (1.f - zz1) * nn1 + zz1 * php[q][nt].y;
                    *reinterpret_cast<float2*>(outs + mrow * HH + c) = make_float2(h0, h1);
                    if (t == TT - 1) {
                        *reinterpret_cast<float2*>(hf + (size_t)n * HH + c) = make_float2(h0, h1);
                    } else {
                        float a0 = h0 * mnx + pg[q][nt].x * (1.f - mnx);
                        float a1 = h1 * mnx + pg[q][nt].y * (1.f - mnx);
                        *reinterpret_cast<float2*>(Awr + (size_t)n * HH + c) = make_float2(a0, a1);
                    }
                }
            }

        // ---- publish own slice for step t+1 ----
        if (t < TT - 1) {
            __threadfence();
            __syncthreads();
            if (tid == 0) {
                unsigned nv = (unsigned)(t + 1);
                asm volatile("st.release.gpu.u32 [%0], %1;" :: "l"(&flags[p * 32]), "r"(nv));
            }
        }
        rb = rbn;
    }
}

__global__ void init_k(const float* __restrict__ hxs, const float* __restrict__ hys,
                       const float* __restrict__ masks, const float* __restrict__ ginit)
{
    int idx = blockIdx.x * blockDim.x + threadIdx.x;
    int cell = idx >> 17;
    int e = idx & (NH - 1);
    int n = e >> 9;
    float m0 = masks[n];
    if (!cell) g_A[0][0][e] = hxs[e] * m0;
    else       g_A[1][0][e] = hys[e] * m0 + ginit[e] * (1.f - m0);
    if (idx < NGROUP * 16) g_flags[idx * 32] = 0u;   // reset ring flags each run
}

extern "C" void kernel_launch(void* const* d_in, const int* in_sizes, int n_in,
                              void* d_out, int out_size)
{
    const float* x     = (const float*)d_in[0];
    const float* hxs   = (const float*)d_in[1];
    const float* hys   = (const float*)d_in[2];
    const float* ginit = (const float*)d_in[3];
    const float* masks = (const float*)d_in[4];
    const float* pah   = (const float*)d_in[5];
    const float* wih   = (const float*)d_in[6];
    const float* whh   = (const float*)d_in[7];
    const float* bih   = (const float*)d_in[8];
    const float* bhh   = (const float*)d_in[9];
    const float* wihp  = (const float*)d_in[10];
    const float* whhp  = (const float*)d_in[11];
    const float* bihp  = (const float*)d_in[12];
    const float* bhhp  = (const float*)d_in[13];
    float* out = (float*)d_out;

    init_k<<<1024, 256>>>(hxs, hys, masks, ginit);

    gi_gemm_k<<<dim3(12, 256), 256>>>(x, wih, wihp, pah, masks, bih, bihp, bhh, bhhp);

    cudaFuncSetAttribute(scan_k, cudaFuncAttributeMaxDynamicSharedMemorySize, SMEM_SCAN);
    scan_k<<<NCTA, 128, SMEM_SCAN>>>(whh, whhp, masks, ginit, bhh, bhhp, out);
}